// round 1
// baseline (speedup 1.0000x reference)
#include <cuda_runtime.h>
#include <cstdint>

#define BB 16
#define HH 1024
#define WW 1024
#define WORDS 32                    // uint32 words per row (W=1024)
#define HW (HH * WW)
#define NPIX (BB * HW)
#define NWORDS (BB * HH * WORDS)

__device__ unsigned int g_tbits[NWORDS];   // packed target bits (2 MiB)
__device__ unsigned int g_ebits[NWORDS];   // packed edge-mask bits (2 MiB)
__device__ unsigned long long g_ecount;
__device__ double g_A;
__device__ double g_B;

// ---------------------------------------------------------------------------
__global__ void k_init() {
    g_ecount = 0ull;
    g_A = 0.0;
    g_B = 0.0;
}

// Pack target (int32 0/1) into bitmasks via warp ballot. One thread per pixel.
__global__ void k_pack(const int* __restrict__ tgt) {
    int tid = blockIdx.x * blockDim.x + threadIdx.x;   // exact NPIX threads
    unsigned w = __ballot_sync(0xffffffffu, tgt[tid] != 0);
    if ((threadIdx.x & 31) == 0) g_tbits[tid >> 5] = w;
}

// Edge mask: e = 1 unless the full 11x11 window (zero-padded) is uniform and
// equal to the center. Bit-parallel: OR/AND across 11 rows, then radius-5
// horizontal dilation with funnel shifts.
__global__ void k_edge() {
    int idx = blockIdx.x * blockDim.x + threadIdx.x;   // word index, exact NWORDS
    int j   = idx & (WORDS - 1);
    int row = idx >> 5;                                // b*H + y
    int y   = row & (HH - 1);
    int rowbase0 = (row - y) * WORDS;                  // word base of (b, y=0)

    unsigned orL = 0, orM = 0, orR = 0;
    unsigned anL = 0xffffffffu, anM = 0xffffffffu, anR = 0xffffffffu;
    #pragma unroll
    for (int d = -5; d <= 5; d++) {
        int r = y + d;
        unsigned wl = 0, wm = 0, wr = 0;
        if (r >= 0 && r < HH) {
            const unsigned* p = g_tbits + rowbase0 + r * WORDS;
            wm = p[j];
            wl = (j > 0)         ? p[j - 1] : 0u;
            wr = (j < WORDS - 1) ? p[j + 1] : 0u;
        }
        orL |= wl; orM |= wm; orR |= wr;
        anL &= wl; anM &= wm; anR &= wr;
    }
    // any-zero path works on complements (padding zeros -> complement ones)
    unsigned nL = ~anL, nM = ~anM, nR = ~anR;
    unsigned any1 = orM, any0 = nM;
    #pragma unroll
    for (int s = 1; s <= 5; s++) {
        any1 |= __funnelshift_r(orM, orR, s);   // bit i gets bit i+s
        any1 |= __funnelshift_l(orL, orM, s);   // bit i gets bit i-s
        any0 |= __funnelshift_r(nM, nR, s);
        any0 |= __funnelshift_l(nL, nM, s);
    }
    unsigned T = g_tbits[idx];
    unsigned e = (T & any0) | (~T & any1);
    g_ebits[idx] = e;

    unsigned c = __popc(e);
    #pragma unroll
    for (int o = 16; o > 0; o >>= 1) c += __shfl_down_sync(0xffffffffu, c, o);
    if ((threadIdx.x & 31) == 0) atomicAdd(&g_ecount, (unsigned long long)c);
}

// Main pass: per-pixel log-softmax (C=2) for both score tensors, accumulate
//   A  += w * (-logp_t)
//   B  += e * w * (0.5*logp_t - logp_other)
__global__ void k_main(const float* __restrict__ s0, const float* __restrict__ s1) {
    const int ngroups = NPIX / 4;
    float accA = 0.f, accB = 0.f;

    for (int g = blockIdx.x * blockDim.x + threadIdx.x; g < ngroups;
         g += gridDim.x * blockDim.x) {
        int pix = g * 4;
        int b   = pix >> 20;          // pix / HW
        int rem = pix & (HW - 1);
        size_t base = (size_t)b * 2 * HW + rem;
        float4 a0 = *(const float4*)(s0 + base);
        float4 a1 = *(const float4*)(s0 + base + HW);
        float4 c0 = *(const float4*)(s1 + base);
        float4 c1 = *(const float4*)(s1 + base + HW);

        unsigned tw = g_tbits[pix >> 5] >> (pix & 31);
        unsigned ew = g_ebits[pix >> 5] >> (pix & 31);

        const float* p0 = &a0.x;
        const float* p1 = &a1.x;
        const float* q0 = &c0.x;
        const float* q1 = &c1.x;
        #pragma unroll
        for (int k = 0; k < 4; k++) {
            bool t = (tw >> k) & 1u;
            bool e = (ew >> k) & 1u;

            float x0 = p0[k], x1 = p1[k];
            float m  = fmaxf(x0, x1);
            float lse = m + log1pf(__expf(fminf(x0, x1) - m));
            float lp0 = x0 - lse, lp1 = x1 - lse;
            float lpt = t ? lp1 : lp0;
            float lpo = t ? lp0 : lp1;

            float y0 = q0[k], y1 = q1[k];
            float m2 = fmaxf(y0, y1);
            float lse2 = m2 + log1pf(__expf(fminf(y0, y1) - m2));
            float l20 = y0 - lse2, l21 = y1 - lse2;
            float lqt = t ? l21 : l20;
            float lqo = t ? l20 : l21;

            accA -= lpt + 0.5f * lqt;
            if (e) accB += (0.5f * lpt - lpo) + 0.5f * (0.5f * lqt - lqo);
        }
    }

    // block reduction
    __shared__ float sA[256];
    __shared__ float sB[256];
    int tid = threadIdx.x;
    sA[tid] = accA;
    sB[tid] = accB;
    __syncthreads();
    #pragma unroll
    for (int s = 128; s > 0; s >>= 1) {
        if (tid < s) {
            sA[tid] += sA[tid + s];
            sB[tid] += sB[tid + s];
        }
        __syncthreads();
    }
    if (tid == 0) {
        atomicAdd(&g_A, (double)sA[0]);
        atomicAdd(&g_B, (double)sB[0]);
    }
}

__global__ void k_final(float* out) {
    double N = (double)NPIX;
    double a = (double)g_ecount / N;
    if (a > 0.2) a = 0.2;
    out[0] = (float)((g_A + a * g_B) / N);
}

// ---------------------------------------------------------------------------
extern "C" void kernel_launch(void* const* d_in, const int* in_sizes, int n_in,
                              void* d_out, int out_size) {
    // identify target = the int32 input (smallest element count); scores keep order
    int ti = 0;
    for (int i = 1; i < n_in; i++)
        if (in_sizes[i] < in_sizes[ti]) ti = i;
    const float* s0 = nullptr;
    const float* s1 = nullptr;
    for (int i = 0; i < n_in; i++) {
        if (i == ti) continue;
        if (!s0) s0 = (const float*)d_in[i];
        else     s1 = (const float*)d_in[i];
    }
    const int* tgt = (const int*)d_in[ti];

    k_init<<<1, 1>>>();
    k_pack<<<NPIX / 256, 256>>>(tgt);
    k_edge<<<NWORDS / 256, 256>>>();
    k_main<<<2048, 256>>>(s0, s1);
    k_final<<<1, 1>>>((float*)d_out);
}

// round 2
// speedup vs baseline: 1.1170x; 1.1170x over previous
#include <cuda_runtime.h>
#include <cstdint>

#define BB 16
#define HH 1024
#define WW 1024
#define WORDS 32                    // uint32 words per row (W=1024)
#define HW (HH * WW)
#define NPIX (BB * HW)
#define NWORDS (BB * HH * WORDS)

__device__ unsigned int g_tbits[NWORDS];   // packed target bits (2 MiB)
__device__ unsigned int g_ebits[NWORDS];   // packed edge-mask bits (2 MiB)
__device__ unsigned long long g_ecount;
__device__ double g_A;
__device__ double g_B;

__device__ __forceinline__ float ex2f(float x) {
    float r; asm("ex2.approx.f32 %0, %1;" : "=f"(r) : "f"(x)); return r;
}

// ---------------------------------------------------------------------------
// Pack target (int32 0/1) into bitmasks via warp ballot; block 0 also zeros
// the global accumulators (safe: later kernels are stream-ordered after this).
__global__ void k_pack(const int* __restrict__ tgt) {
    int tid = blockIdx.x * blockDim.x + threadIdx.x;   // exact NPIX threads
    if (tid == 0) { g_ecount = 0ull; g_A = 0.0; g_B = 0.0; }
    unsigned w = __ballot_sync(0xffffffffu, tgt[tid] != 0);
    if ((threadIdx.x & 31) == 0) g_tbits[tid >> 5] = w;
}

// Edge mask: e = 1 unless the full 11x11 window (zero-padded) is uniform and
// equal to the center. Bit-parallel: OR/AND across 11 rows, then radius-5
// horizontal dilation with funnel shifts.
__global__ void k_edge() {
    int idx = blockIdx.x * blockDim.x + threadIdx.x;   // word index, exact NWORDS
    int j   = idx & (WORDS - 1);
    int row = idx >> 5;                                // b*H + y
    int y   = row & (HH - 1);
    int rowbase0 = (row - y) * WORDS;                  // word base of (b, y=0)

    unsigned orL = 0, orM = 0, orR = 0;
    unsigned anL = 0xffffffffu, anM = 0xffffffffu, anR = 0xffffffffu;
    #pragma unroll
    for (int d = -5; d <= 5; d++) {
        int r = y + d;
        unsigned wl = 0, wm = 0, wr = 0;
        if (r >= 0 && r < HH) {
            const unsigned* p = g_tbits + rowbase0 + r * WORDS;
            wm = p[j];
            wl = (j > 0)         ? p[j - 1] : 0u;
            wr = (j < WORDS - 1) ? p[j + 1] : 0u;
        }
        orL |= wl; orM |= wm; orR |= wr;
        anL &= wl; anM &= wm; anR &= wr;
    }
    unsigned nL = ~anL, nM = ~anM, nR = ~anR;
    unsigned any1 = orM, any0 = nM;
    #pragma unroll
    for (int s = 1; s <= 5; s++) {
        any1 |= __funnelshift_r(orM, orR, s);
        any1 |= __funnelshift_l(orL, orM, s);
        any0 |= __funnelshift_r(nM, nR, s);
        any0 |= __funnelshift_l(nL, nM, s);
    }
    unsigned T = g_tbits[idx];
    unsigned e = (T & any0) | (~T & any1);
    g_ebits[idx] = e;

    unsigned c = __popc(e);
    #pragma unroll
    for (int o = 16; o > 0; o >>= 1) c += __shfl_down_sync(0xffffffffu, c, o);
    if ((threadIdx.x & 31) == 0) atomicAdd(&g_ecount, (unsigned long long)c);
}

// Main pass (log2 domain). Per pixel, per tensor with logit diff d2 = (x1-x0)*log2e,
// u = d2 sign-flipped so target class is "positive":
//   -logp_t / ln2           = sp2(-u) = max(-u,0) + lg2(1 + ex2(-|u|))
//   (0.5*logp_t - logp_o)/ln2 = 0.5*sp2(-u) + u
// Final loss = ln2 * (A + a*B) / N.
__global__ void k_main(const float* __restrict__ s0, const float* __restrict__ s1) {
    const int ngroups = NPIX / 8;
    const float LOG2E = 1.4426950408889634f;
    float accA = 0.f, accB = 0.f;

    for (int g = blockIdx.x * blockDim.x + threadIdx.x; g < ngroups;
         g += gridDim.x * blockDim.x) {
        int pix = g * 8;
        int b   = pix >> 20;          // pix / HW
        int rem = pix & (HW - 1);
        size_t base = (size_t)b * 2 * HW + rem;

        float4 A0 = *(const float4*)(s0 + base);
        float4 A1 = *(const float4*)(s0 + base + 4);
        float4 P0 = *(const float4*)(s0 + base + HW);
        float4 P1 = *(const float4*)(s0 + base + HW + 4);
        float4 C0 = *(const float4*)(s1 + base);
        float4 C1 = *(const float4*)(s1 + base + 4);
        float4 Q0 = *(const float4*)(s1 + base + HW);
        float4 Q1 = *(const float4*)(s1 + base + HW + 4);

        int sh = pix & 31;                      // 0,8,16,24
        unsigned tw = g_tbits[pix >> 5] >> sh;  // low 8 bits valid
        unsigned ew = g_ebits[pix >> 5] >> sh;
        unsigned ntw = ~tw;

        float x0[8] = {A0.x, A0.y, A0.z, A0.w, A1.x, A1.y, A1.z, A1.w};
        float x1[8] = {P0.x, P0.y, P0.z, P0.w, P1.x, P1.y, P1.z, P1.w};
        float y0[8] = {C0.x, C0.y, C0.z, C0.w, C1.x, C1.y, C1.z, C1.w};
        float y1[8] = {Q0.x, Q0.y, Q0.z, Q0.w, Q1.x, Q1.y, Q1.z, Q1.w};

        #pragma unroll
        for (int k = 0; k < 8; k++) {
            unsigned sflip = (ntw << (31 - k)) & 0x80000000u;  // sign-flip if t==0
            int      emask = ((int)(ew << (31 - k))) >> 31;    // all-ones if edge

            float d2 = (x1[k] - x0[k]) * LOG2E;
            float u  = __int_as_float(__float_as_int(d2) ^ sflip);
            float z  = ex2f(-fabsf(u));
            float sp = fmaxf(-u, 0.f) + __log2f(1.f + z);

            float e2 = (y1[k] - y0[k]) * LOG2E;
            float v  = __int_as_float(__float_as_int(e2) ^ sflip);
            float z2 = ex2f(-fabsf(v));
            float sq = fmaxf(-v, 0.f) + __log2f(1.f + z2);

            accA += sp + 0.5f * sq;
            float Bt = (0.5f * sp + u) + 0.5f * (0.5f * sq + v);
            accB += __int_as_float(__float_as_int(Bt) & emask);
        }
    }

    // block reduction
    __shared__ float sA[256];
    __shared__ float sB[256];
    int tid = threadIdx.x;
    sA[tid] = accA;
    sB[tid] = accB;
    __syncthreads();
    #pragma unroll
    for (int s = 128; s > 0; s >>= 1) {
        if (tid < s) {
            sA[tid] += sA[tid + s];
            sB[tid] += sB[tid + s];
        }
        __syncthreads();
    }
    if (tid == 0) {
        atomicAdd(&g_A, (double)sA[0]);
        atomicAdd(&g_B, (double)sB[0]);
    }
}

__global__ void k_final(float* out) {
    const double LN2 = 0.6931471805599453;
    double N = (double)NPIX;
    double a = (double)g_ecount / N;
    if (a > 0.2) a = 0.2;
    out[0] = (float)((g_A + a * g_B) * LN2 / N);
}

// ---------------------------------------------------------------------------
extern "C" void kernel_launch(void* const* d_in, const int* in_sizes, int n_in,
                              void* d_out, int out_size) {
    int ti = 0;
    for (int i = 1; i < n_in; i++)
        if (in_sizes[i] < in_sizes[ti]) ti = i;
    const float* s0 = nullptr;
    const float* s1 = nullptr;
    for (int i = 0; i < n_in; i++) {
        if (i == ti) continue;
        if (!s0) s0 = (const float*)d_in[i];
        else     s1 = (const float*)d_in[i];
    }
    const int* tgt = (const int*)d_in[ti];

    k_pack<<<NPIX / 256, 256>>>(tgt);
    k_edge<<<NWORDS / 256, 256>>>();
    k_main<<<2048, 256>>>(s0, s1);
    k_final<<<1, 1>>>((float*)d_out);
}

// round 3
// speedup vs baseline: 1.4932x; 1.3369x over previous
#include <cuda_runtime.h>
#include <cstdint>

#define BB 16
#define HH 1024
#define WW 1024
#define WORDS 32                    // uint32 words per row (W=1024)
#define HW (HH * WW)
#define NPIX (BB * HW)
#define NWORDS (BB * HH * WORDS)

#define NBLK 592                    // 148 SMs * 4 blocks — co-resident by construction
#define NTHR 256
#define NTHREADS (NBLK * NTHR)
#define NWARPS (NTHREADS / 32)

__device__ unsigned int g_tbits[NWORDS];   // packed target bits (2 MiB)
__device__ unsigned int g_ebits[NWORDS];   // packed edge-mask bits (2 MiB)
__device__ unsigned long long g_ecount;
__device__ double g_A;
__device__ double g_B;

// grid-barrier state (all statically zero; restored to zero before kernel exit)
__device__ unsigned g_c1, g_c2, g_c3, g_d3;
__device__ volatile unsigned g_f1, g_f2, g_f3;

__device__ __forceinline__ float ex2f(float x) {
    float r; asm("ex2.approx.f32 %0, %1;" : "=f"(r) : "f"(x)); return r;
}

__device__ __forceinline__ void bar_wait(unsigned* cnt, volatile unsigned* flag) {
    __syncthreads();
    if (threadIdx.x == 0) {
        __threadfence();
        if (atomicAdd(cnt, 1u) == NBLK - 1) {
            *flag = 1u;
        } else {
            while (*flag == 0u) __nanosleep(64);
        }
        __threadfence();
    }
    __syncthreads();
}

__global__ void __launch_bounds__(NTHR, 4)
k_fused(const float* __restrict__ s0, const float* __restrict__ s1,
        const int* __restrict__ tgt, float* __restrict__ out) {
    const int tid   = threadIdx.x;
    const int gtid  = blockIdx.x * NTHR + tid;
    const int lane  = tid & 31;
    const int gwarp = gtid >> 5;

    // ---------------- Phase 1: reset accumulators + pack target bits --------
    if (gtid == 0) { g_ecount = 0ull; g_A = 0.0; g_B = 0.0; }

    for (int w = gwarp; w < NPIX / 128; w += NWARPS) {
        int base = w * 128;
        int t0 = tgt[base + lane];
        int t1 = tgt[base + 32 + lane];
        int t2 = tgt[base + 64 + lane];
        int t3 = tgt[base + 96 + lane];
        unsigned b0 = __ballot_sync(0xffffffffu, t0 != 0);
        unsigned b1 = __ballot_sync(0xffffffffu, t1 != 0);
        unsigned b2 = __ballot_sync(0xffffffffu, t2 != 0);
        unsigned b3 = __ballot_sync(0xffffffffu, t3 != 0);
        if (lane == 0)
            *(uint4*)&g_tbits[w * 4] = make_uint4(b0, b1, b2, b3);
    }

    bar_wait(&g_c1, &g_f1);

    // ---------------- Phase 2: edge mask (bit-parallel 11x11) ---------------
    for (int idx = gtid; idx < NWORDS; idx += NTHREADS) {
        int j   = idx & (WORDS - 1);
        int row = idx >> 5;                      // b*H + y
        int y   = row & (HH - 1);
        int rowbase0 = (row - y) * WORDS;

        unsigned orL = 0, orM = 0, orR = 0;
        unsigned anL = 0xffffffffu, anM = 0xffffffffu, anR = 0xffffffffu;
        #pragma unroll
        for (int d = -5; d <= 5; d++) {
            int r = y + d;
            unsigned wl = 0, wm = 0, wr = 0;
            if (r >= 0 && r < HH) {
                const unsigned* p = g_tbits + rowbase0 + r * WORDS;
                wm = p[j];
                wl = (j > 0)         ? p[j - 1] : 0u;
                wr = (j < WORDS - 1) ? p[j + 1] : 0u;
            }
            orL |= wl; orM |= wm; orR |= wr;
            anL &= wl; anM &= wm; anR &= wr;
        }
        unsigned nL = ~anL, nM = ~anM, nR = ~anR;
        unsigned any1 = orM, any0 = nM;
        #pragma unroll
        for (int s = 1; s <= 5; s++) {
            any1 |= __funnelshift_r(orM, orR, s);
            any1 |= __funnelshift_l(orL, orM, s);
            any0 |= __funnelshift_r(nM, nR, s);
            any0 |= __funnelshift_l(nL, nM, s);
        }
        unsigned T = g_tbits[idx];
        unsigned e = (T & any0) | (~T & any1);
        g_ebits[idx] = e;

        unsigned c = __popc(e);
        #pragma unroll
        for (int o = 16; o > 0; o >>= 1) c += __shfl_down_sync(0xffffffffu, c, o);
        if (lane == 0) atomicAdd(&g_ecount, (unsigned long long)c);
    }

    bar_wait(&g_c2, &g_f2);

    // ---------------- Phase 3: main streaming pass (log2 domain) ------------
    // Per pixel/tensor, u = (x1-x0)*log2e sign-flipped so target class positive:
    //   -logp_t/ln2            = sp2(-u) = max(-u,0)+lg2(1+ex2(-|u|))
    //   (0.5*logp_t-logp_o)/ln2 = 0.5*sp2(-u) + u
    {
        const float LOG2E = 1.4426950408889634f;
        float accA = 0.f, accB = 0.f;

        for (int g = gtid; g < NPIX / 8; g += NTHREADS) {
            int pix = g * 8;
            int b   = pix >> 20;
            int rem = pix & (HW - 1);
            size_t base = (size_t)b * 2 * HW + rem;

            float4 A0 = *(const float4*)(s0 + base);
            float4 A1 = *(const float4*)(s0 + base + 4);
            float4 P0 = *(const float4*)(s0 + base + HW);
            float4 P1 = *(const float4*)(s0 + base + HW + 4);
            float4 C0 = *(const float4*)(s1 + base);
            float4 C1 = *(const float4*)(s1 + base + 4);
            float4 Q0 = *(const float4*)(s1 + base + HW);
            float4 Q1 = *(const float4*)(s1 + base + HW + 4);

            int sh = pix & 31;
            unsigned tw = g_tbits[pix >> 5] >> sh;
            unsigned ew = g_ebits[pix >> 5] >> sh;
            unsigned ntw = ~tw;

            float x0[8] = {A0.x, A0.y, A0.z, A0.w, A1.x, A1.y, A1.z, A1.w};
            float x1[8] = {P0.x, P0.y, P0.z, P0.w, P1.x, P1.y, P1.z, P1.w};
            float y0[8] = {C0.x, C0.y, C0.z, C0.w, C1.x, C1.y, C1.z, C1.w};
            float y1[8] = {Q0.x, Q0.y, Q0.z, Q0.w, Q1.x, Q1.y, Q1.z, Q1.w};

            #pragma unroll
            for (int k = 0; k < 8; k++) {
                unsigned sflip = (ntw << (31 - k)) & 0x80000000u;
                int      emask = ((int)(ew << (31 - k))) >> 31;

                float d2 = (x1[k] - x0[k]) * LOG2E;
                float u  = __int_as_float(__float_as_int(d2) ^ sflip);
                float z  = ex2f(-fabsf(u));
                float sp = fmaxf(-u, 0.f) + __log2f(1.f + z);

                float e2 = (y1[k] - y0[k]) * LOG2E;
                float v  = __int_as_float(__float_as_int(e2) ^ sflip);
                float z2 = ex2f(-fabsf(v));
                float sq = fmaxf(-v, 0.f) + __log2f(1.f + z2);

                accA += sp + 0.5f * sq;
                float Bt = (0.5f * sp + u) + 0.5f * (0.5f * sq + v);
                accB += __int_as_float(__float_as_int(Bt) & emask);
            }
        }

        __shared__ float sA[NTHR];
        __shared__ float sB[NTHR];
        sA[tid] = accA;
        sB[tid] = accB;
        __syncthreads();
        #pragma unroll
        for (int s = NTHR / 2; s > 0; s >>= 1) {
            if (tid < s) { sA[tid] += sA[tid + s]; sB[tid] += sB[tid + s]; }
            __syncthreads();
        }
        if (tid == 0) {
            atomicAdd(&g_A, (double)sA[0]);
            atomicAdd(&g_B, (double)sB[0]);
        }
    }

    // ------- Barrier 3: last arriver also resets barrier-1/2 state ----------
    __syncthreads();
    if (tid == 0) {
        __threadfence();
        if (atomicAdd(&g_c3, 1u) == NBLK - 1) {
            g_c1 = 0; g_f1 = 0;              // all blocks provably departed b1/b2
            g_c2 = 0; g_f2 = 0;
            __threadfence();
            g_f3 = 1u;
        } else {
            while (g_f3 == 0u) __nanosleep(64);
        }
        __threadfence();
    }
    __syncthreads();

    // ---------------- Phase 4: finalize (block 0) ---------------------------
    if (gtid == 0) {
        const double LN2 = 0.6931471805599453;
        double N = (double)NPIX;
        double a = (double)g_ecount / N;
        if (a > 0.2) a = 0.2;
        out[0] = (float)((g_A + a * g_B) * LN2 / N);
    }

    // departure: last block out resets barrier-3 state for next graph replay
    if (tid == 0) {
        if (atomicAdd(&g_d3, 1u) == NBLK - 1) {
            g_c3 = 0; g_f3 = 0; g_d3 = 0;
            __threadfence();
        }
    }
}

// ---------------------------------------------------------------------------
extern "C" void kernel_launch(void* const* d_in, const int* in_sizes, int n_in,
                              void* d_out, int out_size) {
    int ti = 0;
    for (int i = 1; i < n_in; i++)
        if (in_sizes[i] < in_sizes[ti]) ti = i;
    const float* s0 = nullptr;
    const float* s1 = nullptr;
    for (int i = 0; i < n_in; i++) {
        if (i == ti) continue;
        if (!s0) s0 = (const float*)d_in[i];
        else     s1 = (const float*)d_in[i];
    }
    const int* tgt = (const int*)d_in[ti];

    k_fused<<<NBLK, NTHR>>>(s0, s1, tgt, (float*)d_out);
}